// round 10
// baseline (speedup 1.0000x reference)
#include <cuda_runtime.h>

#define EPS 1e-5f
typedef unsigned long long ull;

// ---------------- packed f32x2 helpers (B300 dual-rate FP32 path) ----------
__device__ __forceinline__ ull pack2(float x, float y) {
    ull r; asm("mov.b64 %0, {%1,%2};" : "=l"(r) : "f"(x), "f"(y)); return r;
}
__device__ __forceinline__ ull dup2(float x) { return pack2(x, x); }
__device__ __forceinline__ void unpack2(ull a, float& x, float& y) {
    asm("mov.b64 {%0,%1}, %2;" : "=f"(x), "=f"(y) : "l"(a));
}
__device__ __forceinline__ ull ffma2(ull a, ull b, ull c) {
    ull d; asm("fma.rn.f32x2 %0, %1, %2, %3;" : "=l"(d) : "l"(a), "l"(b), "l"(c));
    return d;
}
__device__ __forceinline__ ull relu2(ull a) {
    float x, y; unpack2(a, x, y);
    x = fmaxf(x, 0.f); y = fmaxf(y, 0.f);
    return pack2(x, y);
}
__device__ __forceinline__ float warp_sum(float v) {
#pragma unroll
    for (int o = 16; o > 0; o >>= 1)
        v += __shfl_down_sync(0xffffffffu, v, o);
    return v;
}

// ---------------- scratch (device globals: no allocs allowed) --------------
__device__ float g_pooled[2 * 768];
__device__ float g_xfeat[2 * 256];
__device__ float g_G1[2 * 153];     // ctrl_w[:, :256] @ x_feat + ctrl_b
__device__ float g_G2[32 * 153];    // ctrl_w[:, 256:] @ te
__device__ float g_part[2 * 16 * 24 * 2];
__device__ float g_stats[2 * 16 * 2];   // (mean, rstd) per (b, group)
__device__ int   g_work;                // k_main work-queue counter

// ============================================================================
// Kernel 1: k_stats — fused independent stats
// ============================================================================
__global__ void k_stats(const float* __restrict__ outp,
                        const float* __restrict__ x,
                        const float* __restrict__ g1g,
                        const float* __restrict__ g1b) {
    __shared__ float rs[256], rss[256];
    int t = threadIdx.x;

    if (blockIdx.x < 768) {
        int bg = blockIdx.x / 24, part = blockIdx.x % 24;
        const float4* base = (const float4*)(outp + (size_t)bg * 786432) + (size_t)part * 8192;
        float s = 0.f, ss = 0.f;
        for (int i = t; i < 8192; i += 256) {
            float4 v = base[i];
            s  += v.x + v.y + v.z + v.w;
            ss += v.x * v.x + v.y * v.y + v.z * v.z + v.w * v.w;
        }
        rs[t] = s; rss[t] = ss;
        __syncthreads();
        for (int o = 128; o > 0; o >>= 1) {
            if (t < o) { rs[t] += rs[t + o]; rss[t] += rss[t + o]; }
            __syncthreads();
        }
        if (t == 0) {
            g_part[blockIdx.x * 2]     = rs[0];
            g_part[blockIdx.x * 2 + 1] = rss[0];
        }
    } else {
        int bg = blockIdx.x - 768;            // 0..31
        int b = bg >> 4, g = bg & 15;
        const float* base = x + ((size_t)b * 768 + (size_t)g * 48) * 512;

        float s = 0.f, ss = 0.f;
        const float4* b4 = (const float4*)base;
        for (int i = t; i < 6144; i += 256) {
            float4 v = b4[i];
            s  += v.x + v.y + v.z + v.w;
            ss += v.x * v.x + v.y * v.y + v.z * v.z + v.w * v.w;
        }
        rs[t] = s; rss[t] = ss;
        __syncthreads();
        for (int o = 128; o > 0; o >>= 1) {
            if (t < o) { rs[t] += rs[t + o]; rss[t] += rss[t + o]; }
            __syncthreads();
        }
        __shared__ float s_mean, s_rstd;
        if (t == 0) {
            float mean = rs[0] * (1.f / 24576.f);
            float var  = rss[0] * (1.f / 24576.f) - mean * mean;
            s_mean = mean;
            s_rstd = rsqrtf(var + EPS);
        }
        __syncthreads();
        float mean = s_mean, rstd = s_rstd;

        int warp = t >> 5, lane = t & 31;
        for (int c = warp; c < 48; c += 8) {
            int ch = g * 48 + c;
            float sc = rstd * g1g[ch];
            float sh = g1b[ch] - mean * sc;
            const float* cb = base + (size_t)c * 512;
            float acc = 0.f;
            for (int i = lane; i < 512; i += 32)
                acc += fmaxf(fmaf(cb[i], sc, sh), 0.f);
            acc = warp_sum(acc);
            if (lane == 0) g_pooled[b * 768 + ch] = acc * (1.f / 512.f);
        }
    }
}

// ============================================================================
// Kernel 2: x_feat = pooled @ gap_w.T + gap_b   (2,256)
// ============================================================================
__global__ void k_xfeat(const float* __restrict__ gap_w,
                        const float* __restrict__ gap_b) {
    int b   = blockIdx.x >> 3;
    int sub = blockIdx.x & 7;
    int warp = threadIdx.x >> 5, lane = threadIdx.x & 31;

    __shared__ float sp[768];
    for (int i = threadIdx.x; i < 768; i += 256) sp[i] = g_pooled[b * 768 + i];
    __syncthreads();

    for (int q = 0; q < 4; q++) {
        int f = sub * 32 + q * 8 + warp;
        const float* wr = gap_w + (size_t)f * 768;
        float acc = 0.f;
        for (int i = lane; i < 768; i += 32)
            acc = fmaf(wr[i], sp[i], acc);
        acc = warp_sum(acc);
        if (lane == 0) g_xfeat[b * 256 + f] = acc + gap_b[f];
    }
}

// ============================================================================
// Kernel 3: k_gparams — flat warp-per-row + gn2 finalize + work-counter reset
// ============================================================================
__global__ void k_gparams(const float* __restrict__ ctrl_w,
                          const float* __restrict__ ctrl_b,
                          const float* __restrict__ te) {
    int blk = blockIdx.x;
    int t = threadIdx.x;

    if (blk == 34) {
        if (t == 0) g_work = 0;           // reset k_main work queue every launch
        if (t < 32) {
            int bg = t;
            float s = 0.f, ss = 0.f;
            for (int p = 0; p < 24; p++) {
                s  += g_part[(bg * 24 + p) * 2];
                ss += g_part[(bg * 24 + p) * 2 + 1];
            }
            float mean = s * (1.f / 786432.f);
            float var  = ss * (1.f / 786432.f) - mean * mean;
            g_stats[bg * 2]     = mean;
            g_stats[bg * 2 + 1] = rsqrtf(var + EPS);
        }
        return;
    }

    __shared__ float sv[256];
    const float* wbase;
    float* dst;
    bool addb = (blk < 2);
    if (addb) {
        if (t < 256) sv[t] = g_xfeat[blk * 256 + t];
        wbase = ctrl_w;
        dst = g_G1 + blk * 153;
    } else {
        int c = blk - 2;
        if (t < 256) sv[t] = te[c * 256 + t];
        wbase = ctrl_w + 256;
        dst = g_G2 + c * 153;
    }
    __syncthreads();

    int warp = t >> 5, lane = t & 31;
    int p0 = warp, p1 = warp + 32, p2 = warp + 64, p3 = warp + 96, p4 = warp + 128;
    bool v4 = (p4 < 153);
    const float* w0 = wbase + (size_t)p0 * 512;
    const float* w1 = wbase + (size_t)p1 * 512;
    const float* w2 = wbase + (size_t)p2 * 512;
    const float* w3 = wbase + (size_t)p3 * 512;
    const float* w4 = wbase + (size_t)(v4 ? p4 : 0) * 512;

    float a0 = 0.f, a1 = 0.f, a2 = 0.f, a3 = 0.f, a4 = 0.f;
#pragma unroll
    for (int it = 0; it < 8; it++) {
        int idx = it * 32 + lane;
        float v = sv[idx];
        a0 = fmaf(w0[idx], v, a0);
        a1 = fmaf(w1[idx], v, a1);
        a2 = fmaf(w2[idx], v, a2);
        a3 = fmaf(w3[idx], v, a3);
        a4 = fmaf(w4[idx], v, a4);
    }
    a0 = warp_sum(a0); a1 = warp_sum(a1); a2 = warp_sum(a2);
    a3 = warp_sum(a3); a4 = warp_sum(a4);
    if (lane == 0) {
        if (addb) {
            dst[p0] = a0 + ctrl_b[p0];
            dst[p1] = a1 + ctrl_b[p1];
            dst[p2] = a2 + ctrl_b[p2];
            dst[p3] = a3 + ctrl_b[p3];
            if (v4) dst[p4] = a4 + ctrl_b[p4];
        } else {
            dst[p0] = a0;
            dst[p1] = a1;
            dst[p2] = a2;
            dst[p3] = a3;
            if (v4) dst[p4] = a4;
        }
    }
}

// ============================================================================
// Kernel 4: persistent k_main — V=1 (one ull/thread), occ 3 (24 warps/SM)
// 1024 chunks of 512 voxels; atomic queue; same math, half the accumulator
// registers -> higher occupancy to cover LDS->FMA latency.
// ============================================================================
__global__ void __launch_bounds__(256, 3)
k_main(const float* __restrict__ outp,
       const float* __restrict__ g2g, const float* __restrict__ g2b,
       const float* __restrict__ pre_w, const float* __restrict__ pre_b,
       float* __restrict__ dst) {
    __shared__ ull s_params[32 * 154];         // pad 154 -> 16B align
    __shared__ ull s_prew[48 * 8];             // transposed [c][o]
    __shared__ ull s_preb[8];
    __shared__ ulonglong2 s_gn[48];            // .x=scale .y=shift (dup2'd)
    __shared__ int s_chunk;

    int t = threadIdx.x;

    for (int i = t; i < 384; i += 256) {
        int c = i >> 3, o = i & 7;
        s_prew[i] = dup2(pre_w[o * 48 + c]);
    }
    if (t < 8) s_preb[t] = dup2(pre_b[t]);

    int cached_b = -1;

    while (true) {
        __syncthreads();
        if (t == 0) s_chunk = atomicAdd(&g_work, 1);
        __syncthreads();
        int chunk = s_chunk;
        if (chunk >= 1024) break;
        int b = chunk >> 9;                    // 512 chunks per batch

        if (b != cached_b) {
            for (int i = t; i < 32 * 154; i += 256) {
                int cls = i / 154, p = i - cls * 154;
                if (p < 153)
                    s_params[i] = dup2(g_G1[b * 153 + p] + g_G2[cls * 153 + p]);
            }
            if (t >= 32 && t < 80) {
                int c = t - 32;
                int g = c / 3;
                float mean = g_stats[(b * 16 + g) * 2];
                float rstd = g_stats[(b * 16 + g) * 2 + 1];
                float sc = rstd * g2g[c];
                s_gn[c].x = dup2(sc);
                s_gn[c].y = dup2(g2b[c] - mean * sc);
            }
            cached_b = b;
            __syncthreads();
        }

        int u0 = (chunk & 511) * 256 + t;      // ull index in [0, 131072)
        const ull* src = (const ull*)outp + (size_t)b * 48 * 131072 + u0;

        ull h0[8];
#pragma unroll
        for (int o = 0; o < 8; o++) h0[o] = s_preb[o];

        // GN2 + ReLU + h0, depth-1 channel prefetch
        ull n0 = src[0];
        for (int c = 0; c < 48; c++) {
            ull v0 = n0;
            if (c < 47) n0 = src[(size_t)(c + 1) * 131072];
            ulonglong2 gn = s_gn[c];
            ull g0 = relu2(ffma2(v0, gn.x, gn.y));
            const ulonglong2* W = (const ulonglong2*)(s_prew + c * 8);
#pragma unroll
            for (int oo = 0; oo < 4; oo++) {
                ulonglong2 w2 = W[oo];
                h0[2 * oo]     = ffma2(w2.x, g0, h0[2 * oo]);
                h0[2 * oo + 1] = ffma2(w2.y, g0, h0[2 * oo + 1]);
            }
        }

        ull* dbase = (ull*)dst + (size_t)b * 32 * 131072 + u0;

        for (int cls = 0; cls < 32; cls++) {
            const ull* P = s_params + cls * 154;
            const ulonglong2* P2 = (const ulonglong2*)P;

            // ---- layer 1: t1 = relu(W1 h0 + b1), biases via LDS.128 ----
            ull t1[8];
#pragma unroll
            for (int jj = 0; jj < 4; jj++) {
                ulonglong2 bb = P2[68 + jj];           // b1[2jj], b1[2jj+1]
                t1[2 * jj]     = bb.x;
                t1[2 * jj + 1] = bb.y;
            }
#pragma unroll
            for (int kk = 0; kk < 4; kk++) {
#pragma unroll
                for (int j = 0; j < 8; j++) {
                    ulonglong2 w2 = P2[j * 4 + kk];
                    t1[j] = ffma2(w2.x, h0[2 * kk],     t1[j]);
                    t1[j] = ffma2(w2.y, h0[2 * kk + 1], t1[j]);
                }
            }
#pragma unroll
            for (int j = 0; j < 8; j++) t1[j] = relu2(t1[j]);

            // ---- layers 2+3 folded ----
            ull y0 = P[152];
#pragma unroll
            for (int jj = 0; jj < 4; jj++) {
                ulonglong2 bb = P2[72 + jj];           // b2[2jj], b2[2jj+1]
#pragma unroll
                for (int h = 0; h < 2; h++) {
                    int j = 2 * jj + h;
                    ull t20 = h ? bb.y : bb.x;
#pragma unroll
                    for (int kk = 0; kk < 4; kk++) {
                        ulonglong2 w2 = P2[32 + j * 4 + kk];
                        t20 = ffma2(w2.x, t1[2 * kk],     t20);
                        t20 = ffma2(w2.y, t1[2 * kk + 1], t20);
                    }
                    y0 = ffma2(P[128 + j], relu2(t20), y0);
                }
            }

            dbase[(size_t)cls * 131072] = y0;
        }
    }
}

// ============================================================================
extern "C" void kernel_launch(void* const* d_in, const int* in_sizes, int n_in,
                              void* d_out, int out_size) {
    const float* x      = (const float*)d_in[0];
    const float* outp   = (const float*)d_in[1];
    const float* te     = (const float*)d_in[2];
    const float* gn1_g  = (const float*)d_in[3];
    const float* gn1_b  = (const float*)d_in[4];
    const float* gap_w  = (const float*)d_in[5];
    const float* gap_b  = (const float*)d_in[6];
    const float* ctrl_w = (const float*)d_in[7];
    const float* ctrl_b = (const float*)d_in[8];
    const float* gn2_g  = (const float*)d_in[9];
    const float* gn2_b  = (const float*)d_in[10];
    const float* pre_w  = (const float*)d_in[11];
    const float* pre_b  = (const float*)d_in[12];
    float* dst = (float*)d_out;

    k_stats<<<800, 256>>>(outp, x, gn1_g, gn1_b);
    k_xfeat<<<16, 256>>>(gap_w, gap_b);
    k_gparams<<<35, 1024>>>(ctrl_w, ctrl_b, te);
    k_main<<<296, 256>>>(outp, gn2_g, gn2_b, pre_w, pre_b, dst);
}

// round 13
// speedup vs baseline: 1.3480x; 1.3480x over previous
#include <cuda_runtime.h>
#include <cstdint>

#define EPS 1e-5f
typedef unsigned long long ull;
typedef unsigned int u32;

// ---------------- packed f32x2 helpers (B300 dual-rate FP32 path) ----------
__device__ __forceinline__ ull pack2(float x, float y) {
    ull r; asm("mov.b64 %0, {%1,%2};" : "=l"(r) : "f"(x), "f"(y)); return r;
}
__device__ __forceinline__ ull dup2(float x) { return pack2(x, x); }
__device__ __forceinline__ void unpack2(ull a, float& x, float& y) {
    asm("mov.b64 {%0,%1}, %2;" : "=f"(x), "=f"(y) : "l"(a));
}
__device__ __forceinline__ ull ffma2(ull a, ull b, ull c) {
    ull d; asm("fma.rn.f32x2 %0, %1, %2, %3;" : "=l"(d) : "l"(a), "l"(b), "l"(c));
    return d;
}
__device__ __forceinline__ ull relu2(ull a) {          // 2x FMNMX (known-good)
    float x, y; unpack2(a, x, y);
    x = fmaxf(x, 0.f); y = fmaxf(y, 0.f);
    return pack2(x, y);
}
__device__ __forceinline__ float warp_sum(float v) {
#pragma unroll
    for (int o = 16; o > 0; o >>= 1)
        v += __shfl_down_sync(0xffffffffu, v, o);
    return v;
}
__device__ __forceinline__ u32 sm2u32(const void* p) {
    u32 a;
    asm("{ .reg .u64 t0; cvta.to.shared.u64 t0, %1; cvt.u32.u64 %0, t0; }"
        : "=r"(a) : "l"(p));
    return a;
}
__device__ __forceinline__ void cp8(u32 saddr, const void* gaddr) {
    asm volatile("cp.async.ca.shared.global [%0], [%1], 8;" :: "r"(saddr), "l"(gaddr));
}
#define CP_COMMIT() asm volatile("cp.async.commit_group;" ::: "memory")
#define CP_WAIT5()  asm volatile("cp.async.wait_group 5;" ::: "memory")

// ---------------- scratch (device globals: no allocs allowed) --------------
__device__ float g_pooled[2 * 768];
__device__ float g_xfeat[2 * 256];
__device__ float g_G1[2 * 153];
__device__ float g_G2[32 * 153];
__device__ float g_part[2 * 16 * 24 * 2];
__device__ float g_stats[2 * 16 * 2];
__device__ int   g_work;

// dynamic smem layout for k_main
#define OFF_PARAMS 0
#define OFF_PREW   39424
#define OFF_PREB   (39424 + 3072)
#define OFF_GN     (39424 + 3072 + 64)
#define OFF_RING   (39424 + 3072 + 64 + 768)     // 43328, 16B aligned
#define SMEM_MAIN  (43328 + 32768)               // 76096 B -> 2 CTAs/SM

// ============================================================================
// Kernel 1: k_stats — fused independent stats
// ============================================================================
__global__ void k_stats(const float* __restrict__ outp,
                        const float* __restrict__ x,
                        const float* __restrict__ g1g,
                        const float* __restrict__ g1b) {
    __shared__ float rs[256], rss[256];
    int t = threadIdx.x;

    if (blockIdx.x < 768) {
        int bg = blockIdx.x / 24, part = blockIdx.x % 24;
        const float4* base = (const float4*)(outp + (size_t)bg * 786432) + (size_t)part * 8192;
        float s = 0.f, ss = 0.f;
        for (int i = t; i < 8192; i += 256) {
            float4 v = base[i];
            s  += v.x + v.y + v.z + v.w;
            ss += v.x * v.x + v.y * v.y + v.z * v.z + v.w * v.w;
        }
        rs[t] = s; rss[t] = ss;
        __syncthreads();
        for (int o = 128; o > 0; o >>= 1) {
            if (t < o) { rs[t] += rs[t + o]; rss[t] += rss[t + o]; }
            __syncthreads();
        }
        if (t == 0) {
            g_part[blockIdx.x * 2]     = rs[0];
            g_part[blockIdx.x * 2 + 1] = rss[0];
        }
    } else {
        int bg = blockIdx.x - 768;
        int b = bg >> 4, g = bg & 15;
        const float* base = x + ((size_t)b * 768 + (size_t)g * 48) * 512;

        float s = 0.f, ss = 0.f;
        const float4* b4 = (const float4*)base;
        for (int i = t; i < 6144; i += 256) {
            float4 v = b4[i];
            s  += v.x + v.y + v.z + v.w;
            ss += v.x * v.x + v.y * v.y + v.z * v.z + v.w * v.w;
        }
        rs[t] = s; rss[t] = ss;
        __syncthreads();
        for (int o = 128; o > 0; o >>= 1) {
            if (t < o) { rs[t] += rs[t + o]; rss[t] += rss[t + o]; }
            __syncthreads();
        }
        __shared__ float s_mean, s_rstd;
        if (t == 0) {
            float mean = rs[0] * (1.f / 24576.f);
            float var  = rss[0] * (1.f / 24576.f) - mean * mean;
            s_mean = mean;
            s_rstd = rsqrtf(var + EPS);
        }
        __syncthreads();
        float mean = s_mean, rstd = s_rstd;

        int warp = t >> 5, lane = t & 31;
        for (int c = warp; c < 48; c += 8) {
            int ch = g * 48 + c;
            float sc = rstd * g1g[ch];
            float sh = g1b[ch] - mean * sc;
            const float* cb = base + (size_t)c * 512;
            float acc = 0.f;
            for (int i = lane; i < 512; i += 32)
                acc += fmaxf(fmaf(cb[i], sc, sh), 0.f);
            acc = warp_sum(acc);
            if (lane == 0) g_pooled[b * 768 + ch] = acc * (1.f / 512.f);
        }
    }
}

// ============================================================================
// Kernel 2: x_feat = pooled @ gap_w.T + gap_b
// ============================================================================
__global__ void k_xfeat(const float* __restrict__ gap_w,
                        const float* __restrict__ gap_b) {
    int b   = blockIdx.x >> 3;
    int sub = blockIdx.x & 7;
    int warp = threadIdx.x >> 5, lane = threadIdx.x & 31;

    __shared__ float sp[768];
    for (int i = threadIdx.x; i < 768; i += 256) sp[i] = g_pooled[b * 768 + i];
    __syncthreads();

    for (int q = 0; q < 4; q++) {
        int f = sub * 32 + q * 8 + warp;
        const float* wr = gap_w + (size_t)f * 768;
        float acc = 0.f;
        for (int i = lane; i < 768; i += 32)
            acc = fmaf(wr[i], sp[i], acc);
        acc = warp_sum(acc);
        if (lane == 0) g_xfeat[b * 256 + f] = acc + gap_b[f];
    }
}

// ============================================================================
// Kernel 3: k_gparams — flat warp-per-row + gn2 finalize + work-counter reset
// ============================================================================
__global__ void k_gparams(const float* __restrict__ ctrl_w,
                          const float* __restrict__ ctrl_b,
                          const float* __restrict__ te) {
    int blk = blockIdx.x;
    int t = threadIdx.x;

    if (blk == 34) {
        if (t == 0) g_work = 0;
        if (t < 32) {
            int bg = t;
            float s = 0.f, ss = 0.f;
            for (int p = 0; p < 24; p++) {
                s  += g_part[(bg * 24 + p) * 2];
                ss += g_part[(bg * 24 + p) * 2 + 1];
            }
            float mean = s * (1.f / 786432.f);
            float var  = ss * (1.f / 786432.f) - mean * mean;
            g_stats[bg * 2]     = mean;
            g_stats[bg * 2 + 1] = rsqrtf(var + EPS);
        }
        return;
    }

    __shared__ float sv[256];
    const float* wbase;
    float* dst;
    bool addb = (blk < 2);
    if (addb) {
        if (t < 256) sv[t] = g_xfeat[blk * 256 + t];
        wbase = ctrl_w;
        dst = g_G1 + blk * 153;
    } else {
        int c = blk - 2;
        if (t < 256) sv[t] = te[c * 256 + t];
        wbase = ctrl_w + 256;
        dst = g_G2 + c * 153;
    }
    __syncthreads();

    int warp = t >> 5, lane = t & 31;
    int p0 = warp, p1 = warp + 32, p2 = warp + 64, p3 = warp + 96, p4 = warp + 128;
    bool v4 = (p4 < 153);
    const float* w0 = wbase + (size_t)p0 * 512;
    const float* w1 = wbase + (size_t)p1 * 512;
    const float* w2 = wbase + (size_t)p2 * 512;
    const float* w3 = wbase + (size_t)p3 * 512;
    const float* w4 = wbase + (size_t)(v4 ? p4 : 0) * 512;

    float a0 = 0.f, a1 = 0.f, a2 = 0.f, a3 = 0.f, a4 = 0.f;
#pragma unroll
    for (int it = 0; it < 8; it++) {
        int idx = it * 32 + lane;
        float v = sv[idx];
        a0 = fmaf(w0[idx], v, a0);
        a1 = fmaf(w1[idx], v, a1);
        a2 = fmaf(w2[idx], v, a2);
        a3 = fmaf(w3[idx], v, a3);
        a4 = fmaf(w4[idx], v, a4);
    }
    a0 = warp_sum(a0); a1 = warp_sum(a1); a2 = warp_sum(a2);
    a3 = warp_sum(a3); a4 = warp_sum(a4);
    if (lane == 0) {
        if (addb) {
            dst[p0] = a0 + ctrl_b[p0];
            dst[p1] = a1 + ctrl_b[p1];
            dst[p2] = a2 + ctrl_b[p2];
            dst[p3] = a3 + ctrl_b[p3];
            if (v4) dst[p4] = a4 + ctrl_b[p4];
        } else {
            dst[p0] = a0;
            dst[p1] = a1;
            dst[p2] = a2;
            dst[p3] = a3;
            if (v4) dst[p4] = a4;
        }
    }
}

// ============================================================================
// Kernel 4: persistent k_main, V=2, cp.async depth-6 smem ring for GN loads
// ============================================================================
__global__ void __launch_bounds__(256, 2)
k_main(const float* __restrict__ outp,
       const float* __restrict__ g2g, const float* __restrict__ g2b,
       const float* __restrict__ pre_w, const float* __restrict__ pre_b,
       float* __restrict__ dst) {
    extern __shared__ char dyn[];
    ull*        s_params = (ull*)(dyn + OFF_PARAMS);   // 32*154 ull
    ull*        s_prew   = (ull*)(dyn + OFF_PREW);     // 48*8 ull
    ull*        s_preb   = (ull*)(dyn + OFF_PREB);     // 8 ull
    ulonglong2* s_gn     = (ulonglong2*)(dyn + OFF_GN);// 48
    ull*        s_ring   = (ull*)(dyn + OFF_RING);     // 8 stages * 512 ull
    __shared__ int s_chunk;

    int t = threadIdx.x;
    u32 ring0 = sm2u32(s_ring) + t * 8;                // this thread's slot 0

    for (int i = t; i < 384; i += 256) {
        int c = i >> 3, o = i & 7;
        s_prew[i] = dup2(pre_w[o * 48 + c]);
    }
    if (t < 8) s_preb[t] = dup2(pre_b[t]);

    int cached_b = -1;

    while (true) {
        __syncthreads();
        if (t == 0) s_chunk = atomicAdd(&g_work, 1);
        __syncthreads();
        int chunk = s_chunk;
        if (chunk >= 512) break;
        int b = chunk >> 8;

        if (b != cached_b) {
            for (int i = t; i < 32 * 154; i += 256) {
                int cls = i / 154, p = i - cls * 154;
                if (p < 153)
                    s_params[i] = dup2(g_G1[b * 153 + p] + g_G2[cls * 153 + p]);
            }
            if (t >= 32 && t < 80) {
                int c = t - 32;
                int g = c / 3;
                float mean = g_stats[(b * 16 + g) * 2];
                float rstd = g_stats[(b * 16 + g) * 2 + 1];
                float sc = rstd * g2g[c];
                s_gn[c].x = dup2(sc);
                s_gn[c].y = dup2(g2b[c] - mean * sc);
            }
            cached_b = b;
            __syncthreads();
        }

        int u0 = (chunk & 255) * 512 + t;
        const ull* src = (const ull*)outp + (size_t)b * 48 * 131072 + u0;

        // prime the ring: channels 0..5 (one commit group per channel)
#pragma unroll
        for (int c0 = 0; c0 < 6; c0++) {
            const ull* gp = src + (size_t)c0 * 131072;
            u32 sa = ring0 + (u32)(c0 * 4096);               // 512 ull * 8 B
            cp8(sa, gp);
            cp8(sa + 2048, gp + 256);                        // 256 ull * 8 B
            CP_COMMIT();
        }

        ull h0[8][2];
#pragma unroll
        for (int o = 0; o < 8; o++) {
            h0[o][0] = s_preb[o];
            h0[o][1] = s_preb[o];
        }

        for (int c = 0; c < 48; c++) {
            CP_WAIT5();                                      // channel c's group done
            int st = (c & 7) * 512;
            ull v0 = s_ring[st + t];
            ull v1 = s_ring[st + t + 256];
            int cn = c + 6;
            if (cn < 48) {                                   // distance-6 prefetch
                const ull* gp = src + (size_t)cn * 131072;
                u32 sa = ring0 + (u32)((cn & 7) * 4096);
                cp8(sa, gp);
                cp8(sa + 2048, gp + 256);
            }
            CP_COMMIT();                                     // keep group count uniform

            ulonglong2 gn = s_gn[c];
            ull g0 = relu2(ffma2(v0, gn.x, gn.y));
            ull g1 = relu2(ffma2(v1, gn.x, gn.y));
            const ulonglong2* W = (const ulonglong2*)(s_prew + c * 8);
#pragma unroll
            for (int oo = 0; oo < 4; oo++) {
                ulonglong2 w2 = W[oo];
                h0[2 * oo][0]     = ffma2(w2.x, g0, h0[2 * oo][0]);
                h0[2 * oo][1]     = ffma2(w2.x, g1, h0[2 * oo][1]);
                h0[2 * oo + 1][0] = ffma2(w2.y, g0, h0[2 * oo + 1][0]);
                h0[2 * oo + 1][1] = ffma2(w2.y, g1, h0[2 * oo + 1][1]);
            }
        }

        ull* dbase = (ull*)dst + (size_t)b * 32 * 131072 + u0;

        for (int cls = 0; cls < 32; cls++) {
            const ull* P = s_params + cls * 154;
            const ulonglong2* P2 = (const ulonglong2*)P;

            ull t1[8][2];
#pragma unroll
            for (int jj = 0; jj < 4; jj++) {
                ulonglong2 bb = P2[68 + jj];
                t1[2 * jj][0]     = bb.x;
                t1[2 * jj][1]     = bb.x;
                t1[2 * jj + 1][0] = bb.y;
                t1[2 * jj + 1][1] = bb.y;
            }
#pragma unroll
            for (int kk = 0; kk < 4; kk++) {
#pragma unroll
                for (int j = 0; j < 8; j++) {
                    ulonglong2 w2 = P2[j * 4 + kk];
                    t1[j][0] = ffma2(w2.x, h0[2 * kk][0],     t1[j][0]);
                    t1[j][1] = ffma2(w2.x, h0[2 * kk][1],     t1[j][1]);
                    t1[j][0] = ffma2(w2.y, h0[2 * kk + 1][0], t1[j][0]);
                    t1[j][1] = ffma2(w2.y, h0[2 * kk + 1][1], t1[j][1]);
                }
            }
#pragma unroll
            for (int j = 0; j < 8; j++) {
                t1[j][0] = relu2(t1[j][0]);
                t1[j][1] = relu2(t1[j][1]);
            }

            ull y0 = P[152], y1 = P[152];
#pragma unroll
            for (int jj = 0; jj < 4; jj++) {
                ulonglong2 bb = P2[72 + jj];
#pragma unroll
                for (int h = 0; h < 2; h++) {
                    int j = 2 * jj + h;
                    ull bias = h ? bb.y : bb.x;
                    ull t20 = bias, t21 = bias;
#pragma unroll
                    for (int kk = 0; kk < 4; kk++) {
                        ulonglong2 w2 = P2[32 + j * 4 + kk];
                        t20 = ffma2(w2.x, t1[2 * kk][0],     t20);
                        t21 = ffma2(w2.x, t1[2 * kk][1],     t21);
                        t20 = ffma2(w2.y, t1[2 * kk + 1][0], t20);
                        t21 = ffma2(w2.y, t1[2 * kk + 1][1], t21);
                    }
                    ull w3 = P[128 + j];
                    y0 = ffma2(w3, relu2(t20), y0);
                    y1 = ffma2(w3, relu2(t21), y1);
                }
            }

            ull* dp = dbase + (size_t)cls * 131072;
            dp[0]   = y0;
            dp[256] = y1;
        }
    }
}

// ============================================================================
extern "C" void kernel_launch(void* const* d_in, const int* in_sizes, int n_in,
                              void* d_out, int out_size) {
    const float* x      = (const float*)d_in[0];
    const float* outp   = (const float*)d_in[1];
    const float* te     = (const float*)d_in[2];
    const float* gn1_g  = (const float*)d_in[3];
    const float* gn1_b  = (const float*)d_in[4];
    const float* gap_w  = (const float*)d_in[5];
    const float* gap_b  = (const float*)d_in[6];
    const float* ctrl_w = (const float*)d_in[7];
    const float* ctrl_b = (const float*)d_in[8];
    const float* gn2_g  = (const float*)d_in[9];
    const float* gn2_b  = (const float*)d_in[10];
    const float* pre_w  = (const float*)d_in[11];
    const float* pre_b  = (const float*)d_in[12];
    float* dst = (float*)d_out;

    cudaFuncSetAttribute(k_main, cudaFuncAttributeMaxDynamicSharedMemorySize,
                         SMEM_MAIN);

    k_stats<<<800, 256>>>(outp, x, gn1_g, gn1_b);
    k_xfeat<<<16, 256>>>(gap_w, gap_b);
    k_gparams<<<35, 1024>>>(ctrl_w, ctrl_b, te);
    k_main<<<296, 256, SMEM_MAIN>>>(outp, gn2_g, gn2_b, pre_w, pre_b, dst);
}

// round 14
// speedup vs baseline: 1.3698x; 1.0162x over previous
#include <cuda_runtime.h>
#include <cstdint>

#define EPS 1e-5f
typedef unsigned long long ull;

// ---------------- packed f32x2 helpers (B300 dual-rate FP32 path) ----------
__device__ __forceinline__ ull pack2(float x, float y) {
    ull r; asm("mov.b64 %0, {%1,%2};" : "=l"(r) : "f"(x), "f"(y)); return r;
}
__device__ __forceinline__ ull dup2(float x) { return pack2(x, x); }
__device__ __forceinline__ void unpack2(ull a, float& x, float& y) {
    asm("mov.b64 {%0,%1}, %2;" : "=f"(x), "=f"(y) : "l"(a));
}
__device__ __forceinline__ ull ffma2(ull a, ull b, ull c) {
    ull d; asm("fma.rn.f32x2 %0, %1, %2, %3;" : "=l"(d) : "l"(a), "l"(b), "l"(c));
    return d;
}
__device__ __forceinline__ ull relu2(ull a) {
    float x, y; unpack2(a, x, y);
    x = fmaxf(x, 0.f); y = fmaxf(y, 0.f);
    return pack2(x, y);
}
__device__ __forceinline__ float warp_sum(float v) {
#pragma unroll
    for (int o = 16; o > 0; o >>= 1)
        v += __shfl_down_sync(0xffffffffu, v, o);
    return v;
}

// ---------------- scratch (device globals: no allocs allowed) --------------
__device__ float g_pooled[2 * 768];
__device__ float g_xfeat[2 * 256];
__device__ float g_G1[2 * 153];
__device__ float g_G2[32 * 153];
__device__ float g_part[2 * 16 * 24 * 2];
__device__ float g_stats[2 * 16 * 2];
__device__ ull   g_h0[2 * 8 * 131072];     // intermediate h0, float2-packed (16.8 MB)

// ============================================================================
// Kernel 1: k_stats — fused independent stats
//   blocks   0..767: GN2 partial sums over out (2,48,64^3)
//   blocks 768..799: GN1(x)+ReLU+pool -> g_pooled (2,768)
// ============================================================================
__global__ void k_stats(const float* __restrict__ outp,
                        const float* __restrict__ x,
                        const float* __restrict__ g1g,
                        const float* __restrict__ g1b) {
    __shared__ float rs[256], rss[256];
    int t = threadIdx.x;

    if (blockIdx.x < 768) {
        int bg = blockIdx.x / 24, part = blockIdx.x % 24;
        const float4* base = (const float4*)(outp + (size_t)bg * 786432) + (size_t)part * 8192;
        float s = 0.f, ss = 0.f;
        for (int i = t; i < 8192; i += 256) {
            float4 v = base[i];
            s  += v.x + v.y + v.z + v.w;
            ss += v.x * v.x + v.y * v.y + v.z * v.z + v.w * v.w;
        }
        rs[t] = s; rss[t] = ss;
        __syncthreads();
        for (int o = 128; o > 0; o >>= 1) {
            if (t < o) { rs[t] += rs[t + o]; rss[t] += rss[t + o]; }
            __syncthreads();
        }
        if (t == 0) {
            g_part[blockIdx.x * 2]     = rs[0];
            g_part[blockIdx.x * 2 + 1] = rss[0];
        }
    } else {
        int bg = blockIdx.x - 768;
        int b = bg >> 4, g = bg & 15;
        const float* base = x + ((size_t)b * 768 + (size_t)g * 48) * 512;

        float s = 0.f, ss = 0.f;
        const float4* b4 = (const float4*)base;
        for (int i = t; i < 6144; i += 256) {
            float4 v = b4[i];
            s  += v.x + v.y + v.z + v.w;
            ss += v.x * v.x + v.y * v.y + v.z * v.z + v.w * v.w;
        }
        rs[t] = s; rss[t] = ss;
        __syncthreads();
        for (int o = 128; o > 0; o >>= 1) {
            if (t < o) { rs[t] += rs[t + o]; rss[t] += rss[t + o]; }
            __syncthreads();
        }
        __shared__ float s_mean, s_rstd;
        if (t == 0) {
            float mean = rs[0] * (1.f / 24576.f);
            float var  = rss[0] * (1.f / 24576.f) - mean * mean;
            s_mean = mean;
            s_rstd = rsqrtf(var + EPS);
        }
        __syncthreads();
        float mean = s_mean, rstd = s_rstd;

        int warp = t >> 5, lane = t & 31;
        for (int c = warp; c < 48; c += 8) {
            int ch = g * 48 + c;
            float sc = rstd * g1g[ch];
            float sh = g1b[ch] - mean * sc;
            const float* cb = base + (size_t)c * 512;
            float acc = 0.f;
            for (int i = lane; i < 512; i += 32)
                acc += fmaxf(fmaf(cb[i], sc, sh), 0.f);
            acc = warp_sum(acc);
            if (lane == 0) g_pooled[b * 768 + ch] = acc * (1.f / 512.f);
        }
    }
}

// ============================================================================
// Kernel 2: x_feat = pooled @ gap_w.T + gap_b
// ============================================================================
__global__ void k_xfeat(const float* __restrict__ gap_w,
                        const float* __restrict__ gap_b) {
    int b   = blockIdx.x >> 3;
    int sub = blockIdx.x & 7;
    int warp = threadIdx.x >> 5, lane = threadIdx.x & 31;

    __shared__ float sp[768];
    for (int i = threadIdx.x; i < 768; i += 256) sp[i] = g_pooled[b * 768 + i];
    __syncthreads();

    for (int q = 0; q < 4; q++) {
        int f = sub * 32 + q * 8 + warp;
        const float* wr = gap_w + (size_t)f * 768;
        float acc = 0.f;
        for (int i = lane; i < 768; i += 32)
            acc = fmaf(wr[i], sp[i], acc);
        acc = warp_sum(acc);
        if (lane == 0) g_xfeat[b * 256 + f] = acc + gap_b[f];
    }
}

// ============================================================================
// Kernel 3: k_gparams — flat warp-per-row + gn2 finalize
// ============================================================================
__global__ void k_gparams(const float* __restrict__ ctrl_w,
                          const float* __restrict__ ctrl_b,
                          const float* __restrict__ te) {
    int blk = blockIdx.x;
    int t = threadIdx.x;

    if (blk == 34) {
        if (t < 32) {
            int bg = t;
            float s = 0.f, ss = 0.f;
            for (int p = 0; p < 24; p++) {
                s  += g_part[(bg * 24 + p) * 2];
                ss += g_part[(bg * 24 + p) * 2 + 1];
            }
            float mean = s * (1.f / 786432.f);
            float var  = ss * (1.f / 786432.f) - mean * mean;
            g_stats[bg * 2]     = mean;
            g_stats[bg * 2 + 1] = rsqrtf(var + EPS);
        }
        return;
    }

    __shared__ float sv[256];
    const float* wbase;
    float* dst;
    bool addb = (blk < 2);
    if (addb) {
        if (t < 256) sv[t] = g_xfeat[blk * 256 + t];
        wbase = ctrl_w;
        dst = g_G1 + blk * 153;
    } else {
        int c = blk - 2;
        if (t < 256) sv[t] = te[c * 256 + t];
        wbase = ctrl_w + 256;
        dst = g_G2 + c * 153;
    }
    __syncthreads();

    int warp = t >> 5, lane = t & 31;
    int p0 = warp, p1 = warp + 32, p2 = warp + 64, p3 = warp + 96, p4 = warp + 128;
    bool v4 = (p4 < 153);
    const float* w0 = wbase + (size_t)p0 * 512;
    const float* w1 = wbase + (size_t)p1 * 512;
    const float* w2 = wbase + (size_t)p2 * 512;
    const float* w3 = wbase + (size_t)p3 * 512;
    const float* w4 = wbase + (size_t)(v4 ? p4 : 0) * 512;

    float a0 = 0.f, a1 = 0.f, a2 = 0.f, a3 = 0.f, a4 = 0.f;
#pragma unroll
    for (int it = 0; it < 8; it++) {
        int idx = it * 32 + lane;
        float v = sv[idx];
        a0 = fmaf(w0[idx], v, a0);
        a1 = fmaf(w1[idx], v, a1);
        a2 = fmaf(w2[idx], v, a2);
        a3 = fmaf(w3[idx], v, a3);
        a4 = fmaf(w4[idx], v, a4);
    }
    a0 = warp_sum(a0); a1 = warp_sum(a1); a2 = warp_sum(a2);
    a3 = warp_sum(a3); a4 = warp_sum(a4);
    if (lane == 0) {
        if (addb) {
            dst[p0] = a0 + ctrl_b[p0];
            dst[p1] = a1 + ctrl_b[p1];
            dst[p2] = a2 + ctrl_b[p2];
            dst[p3] = a3 + ctrl_b[p3];
            if (v4) dst[p4] = a4 + ctrl_b[p4];
        } else {
            dst[p0] = a0;
            dst[p1] = a1;
            dst[p2] = a2;
            dst[p3] = a3;
            if (v4) dst[p4] = a4;
        }
    }
}

// ============================================================================
// Kernel 4: k_h0 — GN2+ReLU -> h0 = pre_w·g + pre_b, store h0 to global
// grid 512 (2 batches x 256 chunks), 256 threads, V=2
// ============================================================================
__global__ void __launch_bounds__(256)
k_h0(const float* __restrict__ outp,
     const float* __restrict__ g2g, const float* __restrict__ g2b,
     const float* __restrict__ pre_w, const float* __restrict__ pre_b) {
    __shared__ ull s_prew[48 * 8];             // transposed [c][o]
    __shared__ ull s_preb[8];
    __shared__ ulonglong2 s_gn[48];

    int b = blockIdx.x >> 8;
    int chunk = blockIdx.x & 255;
    int t = threadIdx.x;

    for (int i = t; i < 384; i += 256) {
        int c = i >> 3, o = i & 7;
        s_prew[i] = dup2(pre_w[o * 48 + c]);
    }
    if (t < 8) s_preb[t] = dup2(pre_b[t]);
    if (t >= 32 && t < 80) {
        int c = t - 32;
        int g = c / 3;
        float mean = g_stats[(b * 16 + g) * 2];
        float rstd = g_stats[(b * 16 + g) * 2 + 1];
        float sc = rstd * g2g[c];
        s_gn[c].x = dup2(sc);
        s_gn[c].y = dup2(g2b[c] - mean * sc);
    }
    __syncthreads();

    int u0 = chunk * 512 + t;
    const ull* src = (const ull*)outp + (size_t)b * 48 * 131072 + u0;

    ull h0[8][2];
#pragma unroll
    for (int o = 0; o < 8; o++) {
        h0[o][0] = s_preb[o];
        h0[o][1] = s_preb[o];
    }

    ull n0 = src[0], n1 = src[256];
    for (int c = 0; c < 48; c++) {
        ull v0 = n0, v1 = n1;
        if (c < 47) {
            const ull* nx = src + (size_t)(c + 1) * 131072;
            n0 = nx[0]; n1 = nx[256];
        }
        ulonglong2 gn = s_gn[c];
        ull g0 = relu2(ffma2(v0, gn.x, gn.y));
        ull g1 = relu2(ffma2(v1, gn.x, gn.y));
        const ulonglong2* W = (const ulonglong2*)(s_prew + c * 8);
#pragma unroll
        for (int oo = 0; oo < 4; oo++) {
            ulonglong2 w2 = W[oo];
            h0[2 * oo][0]     = ffma2(w2.x, g0, h0[2 * oo][0]);
            h0[2 * oo][1]     = ffma2(w2.x, g1, h0[2 * oo][1]);
            h0[2 * oo + 1][0] = ffma2(w2.y, g0, h0[2 * oo + 1][0]);
            h0[2 * oo + 1][1] = ffma2(w2.y, g1, h0[2 * oo + 1][1]);
        }
    }

    ull* hdst = g_h0 + (size_t)b * 8 * 131072 + u0;
#pragma unroll
    for (int o = 0; o < 8; o++) {
        hdst[(size_t)o * 131072]       = h0[o][0];
        hdst[(size_t)o * 131072 + 256] = h0[o][1];
    }
}

// ============================================================================
// Kernel 5: k_cls — 32-class MLP from h0; one CTA = (b, chunk, 8-class group)
// grid 2048 = 2 x 256 x 4; 256 threads, V=2; 6.92 waves -> 98.9% util
// ============================================================================
__global__ void __launch_bounds__(256, 2)
k_cls(float* __restrict__ dst) {
    __shared__ ull s_params[8 * 154];          // 9856 B

    int b     = blockIdx.x >> 10;
    int rem   = blockIdx.x & 1023;
    int chunk = rem >> 2;
    int cls0  = (rem & 3) * 8;
    int t = threadIdx.x;

    for (int i = t; i < 8 * 154; i += 256) {
        int cl = i / 154, p = i - cl * 154;
        if (p < 153)
            s_params[i] = dup2(g_G1[b * 153 + p] + g_G2[(cls0 + cl) * 153 + p]);
    }
    __syncthreads();

    int u0 = chunk * 512 + t;
    const ull* hsrc = g_h0 + (size_t)b * 8 * 131072 + u0;

    // 16 independent coalesced loads, hoisted: MLP=16 covers DRAM/L2 latency
    ull h0[8][2];
#pragma unroll
    for (int o = 0; o < 8; o++) {
        h0[o][0] = hsrc[(size_t)o * 131072];
        h0[o][1] = hsrc[(size_t)o * 131072 + 256];
    }

    ull* dbase = (ull*)dst + (size_t)b * 32 * 131072 + (size_t)cls0 * 131072 + u0;

    for (int cl = 0; cl < 8; cl++) {
        const ull* P = s_params + cl * 154;
        const ulonglong2* P2 = (const ulonglong2*)P;

        // ---- layer 1: t1 = relu(W1 h0 + b1), biases via LDS.128 ----
        ull t1[8][2];
#pragma unroll
        for (int jj = 0; jj < 4; jj++) {
            ulonglong2 bb = P2[68 + jj];
            t1[2 * jj][0]     = bb.x;
            t1[2 * jj][1]     = bb.x;
            t1[2 * jj + 1][0] = bb.y;
            t1[2 * jj + 1][1] = bb.y;
        }
#pragma unroll
        for (int kk = 0; kk < 4; kk++) {
#pragma unroll
            for (int j = 0; j < 8; j++) {
                ulonglong2 w2 = P2[j * 4 + kk];
                t1[j][0] = ffma2(w2.x, h0[2 * kk][0],     t1[j][0]);
                t1[j][1] = ffma2(w2.x, h0[2 * kk][1],     t1[j][1]);
                t1[j][0] = ffma2(w2.y, h0[2 * kk + 1][0], t1[j][0]);
                t1[j][1] = ffma2(w2.y, h0[2 * kk + 1][1], t1[j][1]);
            }
        }
#pragma unroll
        for (int j = 0; j < 8; j++) {
            t1[j][0] = relu2(t1[j][0]);
            t1[j][1] = relu2(t1[j][1]);
        }

        // ---- layers 2+3 folded ----
        ull y0 = P[152], y1 = P[152];
#pragma unroll
        for (int jj = 0; jj < 4; jj++) {
            ulonglong2 bb = P2[72 + jj];
#pragma unroll
            for (int h = 0; h < 2; h++) {
                int j = 2 * jj + h;
                ull bias = h ? bb.y : bb.x;
                ull t20 = bias, t21 = bias;
#pragma unroll
                for (int kk = 0; kk < 4; kk++) {
                    ulonglong2 w2 = P2[32 + j * 4 + kk];
                    t20 = ffma2(w2.x, t1[2 * kk][0],     t20);
                    t21 = ffma2(w2.x, t1[2 * kk][1],     t21);
                    t20 = ffma2(w2.y, t1[2 * kk + 1][0], t20);
                    t21 = ffma2(w2.y, t1[2 * kk + 1][1], t21);
                }
                ull w3 = P[128 + j];
                y0 = ffma2(w3, relu2(t20), y0);
                y1 = ffma2(w3, relu2(t21), y1);
            }
        }

        ull* dp = dbase + (size_t)cl * 131072;
        dp[0]   = y0;
        dp[256] = y1;
    }
}

// ============================================================================
extern "C" void kernel_launch(void* const* d_in, const int* in_sizes, int n_in,
                              void* d_out, int out_size) {
    const float* x      = (const float*)d_in[0];
    const float* outp   = (const float*)d_in[1];
    const float* te     = (const float*)d_in[2];
    const float* gn1_g  = (const float*)d_in[3];
    const float* gn1_b  = (const float*)d_in[4];
    const float* gap_w  = (const float*)d_in[5];
    const float* gap_b  = (const float*)d_in[6];
    const float* ctrl_w = (const float*)d_in[7];
    const float* ctrl_b = (const float*)d_in[8];
    const float* gn2_g  = (const float*)d_in[9];
    const float* gn2_b  = (const float*)d_in[10];
    const float* pre_w  = (const float*)d_in[11];
    const float* pre_b  = (const float*)d_in[12];
    float* dst = (float*)d_out;

    k_stats<<<800, 256>>>(outp, x, gn1_g, gn1_b);
    k_xfeat<<<16, 256>>>(gap_w, gap_b);
    k_gparams<<<35, 1024>>>(ctrl_w, ctrl_b, te);
    k_h0<<<512, 256>>>(outp, gn2_g, gn2_b, pre_w, pre_b);
    k_cls<<<2048, 256>>>(dst);
}

// round 15
// speedup vs baseline: 1.3976x; 1.0203x over previous
#include <cuda_runtime.h>
#include <cstdint>

#define EPS 1e-5f
typedef unsigned long long ull;

// ---------------- packed f32x2 helpers (B300 dual-rate FP32 path) ----------
__device__ __forceinline__ ull pack2(float x, float y) {
    ull r; asm("mov.b64 %0, {%1,%2};" : "=l"(r) : "f"(x), "f"(y)); return r;
}
__device__ __forceinline__ ull dup2(float x) { return pack2(x, x); }
__device__ __forceinline__ void unpack2(ull a, float& x, float& y) {
    asm("mov.b64 {%0,%1}, %2;" : "=f"(x), "=f"(y) : "l"(a));
}
__device__ __forceinline__ ull ffma2(ull a, ull b, ull c) {
    ull d; asm("fma.rn.f32x2 %0, %1, %2, %3;" : "=l"(d) : "l"(a), "l"(b), "l"(c));
    return d;
}
__device__ __forceinline__ ull relu2(ull a) {
    float x, y; unpack2(a, x, y);
    x = fmaxf(x, 0.f); y = fmaxf(y, 0.f);
    return pack2(x, y);
}
__device__ __forceinline__ float warp_sum(float v) {
#pragma unroll
    for (int o = 16; o > 0; o >>= 1)
        v += __shfl_down_sync(0xffffffffu, v, o);
    return v;
}

// ---------------- scratch (device globals: no allocs allowed) --------------
__device__ float g_pooled[2 * 768];
__device__ float g_xfeat[2 * 256];
__device__ float g_G1[2 * 153];
__device__ float g_G2[32 * 153];
__device__ float g_part[2 * 16 * 24 * 2];
__device__ float g_stats[2 * 16 * 2];
__device__ ull   g_h0[2 * 8 * 131072];     // intermediate h0, float2-packed

// ============================================================================
// Kernel 1: k_stats — fused independent stats
// ============================================================================
__global__ void k_stats(const float* __restrict__ outp,
                        const float* __restrict__ x,
                        const float* __restrict__ g1g,
                        const float* __restrict__ g1b) {
    __shared__ float rs[256], rss[256];
    int t = threadIdx.x;

    if (blockIdx.x < 768) {
        int bg = blockIdx.x / 24, part = blockIdx.x % 24;
        const float4* base = (const float4*)(outp + (size_t)bg * 786432) + (size_t)part * 8192;
        float s = 0.f, ss = 0.f;
        for (int i = t; i < 8192; i += 256) {
            float4 v = base[i];
            s  += v.x + v.y + v.z + v.w;
            ss += v.x * v.x + v.y * v.y + v.z * v.z + v.w * v.w;
        }
        rs[t] = s; rss[t] = ss;
        __syncthreads();
        for (int o = 128; o > 0; o >>= 1) {
            if (t < o) { rs[t] += rs[t + o]; rss[t] += rss[t + o]; }
            __syncthreads();
        }
        if (t == 0) {
            g_part[blockIdx.x * 2]     = rs[0];
            g_part[blockIdx.x * 2 + 1] = rss[0];
        }
    } else {
        int bg = blockIdx.x - 768;
        int b = bg >> 4, g = bg & 15;
        const float* base = x + ((size_t)b * 768 + (size_t)g * 48) * 512;

        float s = 0.f, ss = 0.f;
        const float4* b4 = (const float4*)base;
        for (int i = t; i < 6144; i += 256) {
            float4 v = b4[i];
            s  += v.x + v.y + v.z + v.w;
            ss += v.x * v.x + v.y * v.y + v.z * v.z + v.w * v.w;
        }
        rs[t] = s; rss[t] = ss;
        __syncthreads();
        for (int o = 128; o > 0; o >>= 1) {
            if (t < o) { rs[t] += rs[t + o]; rss[t] += rss[t + o]; }
            __syncthreads();
        }
        __shared__ float s_mean, s_rstd;
        if (t == 0) {
            float mean = rs[0] * (1.f / 24576.f);
            float var  = rss[0] * (1.f / 24576.f) - mean * mean;
            s_mean = mean;
            s_rstd = rsqrtf(var + EPS);
        }
        __syncthreads();
        float mean = s_mean, rstd = s_rstd;

        int warp = t >> 5, lane = t & 31;
        for (int c = warp; c < 48; c += 8) {
            int ch = g * 48 + c;
            float sc = rstd * g1g[ch];
            float sh = g1b[ch] - mean * sc;
            const float* cb = base + (size_t)c * 512;
            float acc = 0.f;
            for (int i = lane; i < 512; i += 32)
                acc += fmaxf(fmaf(cb[i], sc, sh), 0.f);
            acc = warp_sum(acc);
            if (lane == 0) g_pooled[b * 768 + ch] = acc * (1.f / 512.f);
        }
    }
}

// ============================================================================
// Kernel 2: x_feat = pooled @ gap_w.T + gap_b
// ============================================================================
__global__ void k_xfeat(const float* __restrict__ gap_w,
                        const float* __restrict__ gap_b) {
    int b   = blockIdx.x >> 3;
    int sub = blockIdx.x & 7;
    int warp = threadIdx.x >> 5, lane = threadIdx.x & 31;

    __shared__ float sp[768];
    for (int i = threadIdx.x; i < 768; i += 256) sp[i] = g_pooled[b * 768 + i];
    __syncthreads();

    for (int q = 0; q < 4; q++) {
        int f = sub * 32 + q * 8 + warp;
        const float* wr = gap_w + (size_t)f * 768;
        float acc = 0.f;
        for (int i = lane; i < 768; i += 32)
            acc = fmaf(wr[i], sp[i], acc);
        acc = warp_sum(acc);
        if (lane == 0) g_xfeat[b * 256 + f] = acc + gap_b[f];
    }
}

// ============================================================================
// Kernel 3: k_gparams — flat warp-per-row + gn2 finalize
// ============================================================================
__global__ void k_gparams(const float* __restrict__ ctrl_w,
                          const float* __restrict__ ctrl_b,
                          const float* __restrict__ te) {
    int blk = blockIdx.x;
    int t = threadIdx.x;

    if (blk == 34) {
        if (t < 32) {
            int bg = t;
            float s = 0.f, ss = 0.f;
            for (int p = 0; p < 24; p++) {
                s  += g_part[(bg * 24 + p) * 2];
                ss += g_part[(bg * 24 + p) * 2 + 1];
            }
            float mean = s * (1.f / 786432.f);
            float var  = ss * (1.f / 786432.f) - mean * mean;
            g_stats[bg * 2]     = mean;
            g_stats[bg * 2 + 1] = rsqrtf(var + EPS);
        }
        return;
    }

    __shared__ float sv[256];
    const float* wbase;
    float* dst;
    bool addb = (blk < 2);
    if (addb) {
        if (t < 256) sv[t] = g_xfeat[blk * 256 + t];
        wbase = ctrl_w;
        dst = g_G1 + blk * 153;
    } else {
        int c = blk - 2;
        if (t < 256) sv[t] = te[c * 256 + t];
        wbase = ctrl_w + 256;
        dst = g_G2 + c * 153;
    }
    __syncthreads();

    int warp = t >> 5, lane = t & 31;
    int p0 = warp, p1 = warp + 32, p2 = warp + 64, p3 = warp + 96, p4 = warp + 128;
    bool v4 = (p4 < 153);
    const float* w0 = wbase + (size_t)p0 * 512;
    const float* w1 = wbase + (size_t)p1 * 512;
    const float* w2 = wbase + (size_t)p2 * 512;
    const float* w3 = wbase + (size_t)p3 * 512;
    const float* w4 = wbase + (size_t)(v4 ? p4 : 0) * 512;

    float a0 = 0.f, a1 = 0.f, a2 = 0.f, a3 = 0.f, a4 = 0.f;
#pragma unroll
    for (int it = 0; it < 8; it++) {
        int idx = it * 32 + lane;
        float v = sv[idx];
        a0 = fmaf(w0[idx], v, a0);
        a1 = fmaf(w1[idx], v, a1);
        a2 = fmaf(w2[idx], v, a2);
        a3 = fmaf(w3[idx], v, a3);
        a4 = fmaf(w4[idx], v, a4);
    }
    a0 = warp_sum(a0); a1 = warp_sum(a1); a2 = warp_sum(a2);
    a3 = warp_sum(a3); a4 = warp_sum(a4);
    if (lane == 0) {
        if (addb) {
            dst[p0] = a0 + ctrl_b[p0];
            dst[p1] = a1 + ctrl_b[p1];
            dst[p2] = a2 + ctrl_b[p2];
            dst[p3] = a3 + ctrl_b[p3];
            if (v4) dst[p4] = a4 + ctrl_b[p4];
        } else {
            dst[p0] = a0;
            dst[p1] = a1;
            dst[p2] = a2;
            dst[p3] = a3;
            if (v4) dst[p4] = a4;
        }
    }
}

// ============================================================================
// Kernel 4: k_h0 — GN2+ReLU -> h0; 128-thread CTAs, grid 1024 for full MLP
// ============================================================================
__global__ void __launch_bounds__(128)
k_h0(const float* __restrict__ outp,
     const float* __restrict__ g2g, const float* __restrict__ g2b,
     const float* __restrict__ pre_w, const float* __restrict__ pre_b) {
    __shared__ ull s_prew[48 * 8];             // transposed [c][o]
    __shared__ ull s_preb[8];
    __shared__ ulonglong2 s_gn[48];

    int b = blockIdx.x >> 9;                   // 512 chunks per batch
    int chunk = blockIdx.x & 511;
    int t = threadIdx.x;

    for (int i = t; i < 384; i += 128) {
        int c = i >> 3, o = i & 7;
        s_prew[i] = dup2(pre_w[o * 48 + c]);
    }
    if (t < 8) s_preb[t] = dup2(pre_b[t]);
    if (t >= 32 && t < 80) {
        int c = t - 32;
        int g = c / 3;
        float mean = g_stats[(b * 16 + g) * 2];
        float rstd = g_stats[(b * 16 + g) * 2 + 1];
        float sc = rstd * g2g[c];
        s_gn[c].x = dup2(sc);
        s_gn[c].y = dup2(g2b[c] - mean * sc);
    }
    __syncthreads();

    int u0 = chunk * 256 + t;
    const ull* src = (const ull*)outp + (size_t)b * 48 * 131072 + u0;

    ull h0[8][2];
#pragma unroll
    for (int o = 0; o < 8; o++) {
        h0[o][0] = s_preb[o];
        h0[o][1] = s_preb[o];
    }

    ull n0 = src[0], n1 = src[128];
    for (int c = 0; c < 48; c++) {
        ull v0 = n0, v1 = n1;
        if (c < 47) {
            const ull* nx = src + (size_t)(c + 1) * 131072;
            n0 = nx[0]; n1 = nx[128];
        }
        ulonglong2 gn = s_gn[c];
        ull g0 = relu2(ffma2(v0, gn.x, gn.y));
        ull g1 = relu2(ffma2(v1, gn.x, gn.y));
        const ulonglong2* W = (const ulonglong2*)(s_prew + c * 8);
#pragma unroll
        for (int oo = 0; oo < 4; oo++) {
            ulonglong2 w2 = W[oo];
            h0[2 * oo][0]     = ffma2(w2.x, g0, h0[2 * oo][0]);
            h0[2 * oo][1]     = ffma2(w2.x, g1, h0[2 * oo][1]);
            h0[2 * oo + 1][0] = ffma2(w2.y, g0, h0[2 * oo + 1][0]);
            h0[2 * oo + 1][1] = ffma2(w2.y, g1, h0[2 * oo + 1][1]);
        }
    }

    ull* hdst = g_h0 + (size_t)b * 8 * 131072 + u0;
#pragma unroll
    for (int o = 0; o < 8; o++) {
        hdst[(size_t)o * 131072]       = h0[o][0];
        hdst[(size_t)o * 131072 + 128] = h0[o][1];
    }
}

// ============================================================================
// Kernel 5: k_cls — 8 classes per CTA; 128 threads, occ 5 (20 warps/SM)
// grid 4096 = 2 b x 512 chunks x 4 octets
// ============================================================================
__global__ void __launch_bounds__(128, 5)
k_cls(float* __restrict__ dst) {
    __shared__ ull s_params[8 * 154];          // 9856 B

    int b     = blockIdx.x >> 11;
    int rem   = blockIdx.x & 2047;
    int chunk = rem >> 2;                      // 0..511
    int cls0  = (rem & 3) * 8;
    int t = threadIdx.x;

    for (int i = t; i < 8 * 154; i += 128) {
        int cl = i / 154, p = i - cl * 154;
        if (p < 153)
            s_params[i] = dup2(g_G1[b * 153 + p] + g_G2[(cls0 + cl) * 153 + p]);
    }
    __syncthreads();

    int u0 = chunk * 256 + t;
    const ull* hsrc = g_h0 + (size_t)b * 8 * 131072 + u0;

    ull h0[8][2];
#pragma unroll
    for (int o = 0; o < 8; o++) {
        h0[o][0] = hsrc[(size_t)o * 131072];
        h0[o][1] = hsrc[(size_t)o * 131072 + 128];
    }

    ull* dbase = (ull*)dst + (size_t)b * 32 * 131072 + (size_t)cls0 * 131072 + u0;

    for (int cl = 0; cl < 8; cl++) {
        const ull* P = s_params + cl * 154;
        const ulonglong2* P2 = (const ulonglong2*)P;

        // ---- layer 1: t1 = relu(W1 h0 + b1) ----
        ull t1[8][2];
#pragma unroll
        for (int jj = 0; jj < 4; jj++) {
            ulonglong2 bb = P2[68 + jj];
            t1[2 * jj][0]     = bb.x;
            t1[2 * jj][1]     = bb.x;
            t1[2 * jj + 1][0] = bb.y;
            t1[2 * jj + 1][1] = bb.y;
        }
#pragma unroll
        for (int kk = 0; kk < 4; kk++) {
#pragma unroll
            for (int j = 0; j < 8; j++) {
                ulonglong2 w2 = P2[j * 4 + kk];
                t1[j][0] = ffma2(w2.x, h0[2 * kk][0],     t1[j][0]);
                t1[j][1] = ffma2(w2.x, h0[2 * kk][1],     t1[j][1]);
                t1[j][0] = ffma2(w2.y, h0[2 * kk + 1][0], t1[j][0]);
                t1[j][1] = ffma2(w2.y, h0[2 * kk + 1][1], t1[j][1]);
            }
        }
#pragma unroll
        for (int j = 0; j < 8; j++) {
            t1[j][0] = relu2(t1[j][0]);
            t1[j][1] = relu2(t1[j][1]);
        }

        // ---- layers 2+3 folded ----
        ull y0 = P[152], y1 = P[152];
#pragma unroll
        for (int jj = 0; jj < 4; jj++) {
            ulonglong2 bb = P2[72 + jj];
#pragma unroll
            for (int h = 0; h < 2; h++) {
                int j = 2 * jj + h;
                ull bias = h ? bb.y : bb.x;
                ull t20 = bias, t21 = bias;
#pragma unroll
                for (int kk = 0; kk < 4; kk++) {
                    ulonglong2 w2 = P2[32 + j * 4 + kk];
                    t20 = ffma2(w2.x, t1[2 * kk][0],     t20);
                    t21 = ffma2(w2.x, t1[2 * kk][1],     t21);
                    t20 = ffma2(w2.y, t1[2 * kk + 1][0], t20);
                    t21 = ffma2(w2.y, t1[2 * kk + 1][1], t21);
                }
                ull w3 = P[128 + j];
                y0 = ffma2(w3, relu2(t20), y0);
                y1 = ffma2(w3, relu2(t21), y1);
            }
        }

        ull* dp = dbase + (size_t)cl * 131072;
        dp[0]   = y0;
        dp[128] = y1;
    }
}

// ============================================================================
extern "C" void kernel_launch(void* const* d_in, const int* in_sizes, int n_in,
                              void* d_out, int out_size) {
    const float* x      = (const float*)d_in[0];
    const float* outp   = (const float*)d_in[1];
    const float* te     = (const float*)d_in[2];
    const float* gn1_g  = (const float*)d_in[3];
    const float* gn1_b  = (const float*)d_in[4];
    const float* gap_w  = (const float*)d_in[5];
    const float* gap_b  = (const float*)d_in[6];
    const float* ctrl_w = (const float*)d_in[7];
    const float* ctrl_b = (const float*)d_in[8];
    const float* gn2_g  = (const float*)d_in[9];
    const float* gn2_b  = (const float*)d_in[10];
    const float* pre_w  = (const float*)d_in[11];
    const float* pre_b  = (const float*)d_in[12];
    float* dst = (float*)d_out;

    k_stats<<<800, 256>>>(outp, x, gn1_g, gn1_b);
    k_xfeat<<<16, 256>>>(gap_w, gap_b);
    k_gparams<<<35, 1024>>>(ctrl_w, ctrl_b, te);
    k_h0<<<1024, 128>>>(outp, gn2_g, gn2_b, pre_w, pre_b);
    k_cls<<<4096, 128>>>(dst);
}